// round 7
// baseline (speedup 1.0000x reference)
#include <cuda_runtime.h>
#include <cuda_bf16.h>

// Problem: 4 feature pyramids f0[4,64,256,256] f1[4,128,128,128]
// f2[4,256,64,64] f3[4,512,32,32], indices[4096] into flattened 256x256.
// Reference: bilinear-resize each level to 256x256 (half-pixel centers,
// edge weight renormalization == clamp-to-edge for upsampling), gather
// indices, concat channels -> out [4, 960, 4096] fp32.
//
// Fused: gather-with-bilinear-sampling directly from each source level.
// Level 0 (scale 1) degenerates to an identity gather. S is a template
// parameter so strides/shifts resolve at compile time.

#define NIDX 4096
#define CPT  8          // channels per thread (amortize geometry, raise MLP)
#define TPB  256

template <int S, int C>
__device__ __forceinline__ void sample_level(
    const float* __restrict__ f, const int* __restrict__ indices,
    float* __restrict__ out, int i, int clocal, int cglobal, int b)
{
    const int idx = __ldg(indices + i);
    constexpr int plane = S * S;
    const float* base = f + (size_t)(b * C + clocal) * plane;
    float* obase = out + ((size_t)b * 960 + cglobal) * NIDX + i;

    if constexpr (S == 256) {
        // Identity gather (scale == 1).
        #pragma unroll
        for (int k = 0; k < CPT; k++)
            obase[(size_t)k * NIDX] = __ldg(base + (size_t)k * plane + idx);
        return;
    } else {
        const int y = idx >> 8;
        const int x = idx & 255;

        // Half-pixel bilinear: src = (dst + 0.5) * (S/256) - 0.5.
        constexpr float scale = (float)S * (1.0f / 256.0f);
        const float fy = ((float)y + 0.5f) * scale - 0.5f;
        const float fx = ((float)x + 0.5f) * scale - 0.5f;
        const float fy0 = floorf(fy);
        const float fx0 = floorf(fx);
        const float wy = fy - fy0;
        const float wx = fx - fx0;
        int y0 = (int)fy0, x0 = (int)fx0;
        int y1 = y0 + 1,   x1 = x0 + 1;
        // clamp to edge (== jax boundary renormalization for upsampling)
        y0 = min(max(y0, 0), S - 1);
        y1 = min(max(y1, 0), S - 1);
        x0 = min(max(x0, 0), S - 1);
        x1 = min(max(x1, 0), S - 1);

        const int o00 = y0 * S + x0;
        const int o01 = y0 * S + x1;
        const int o10 = y1 * S + x0;
        const int o11 = y1 * S + x1;

        const float w00 = (1.0f - wy) * (1.0f - wx);
        const float w01 = (1.0f - wy) * wx;
        const float w10 = wy * (1.0f - wx);
        const float w11 = wy * wx;

        #pragma unroll
        for (int k = 0; k < CPT; k++) {
            const float* p = base + (size_t)k * plane;
            // Taps issued before any consumer -> front-batched LDGs (MLP).
            float v00 = __ldg(p + o00);
            float v01 = __ldg(p + o01);
            float v10 = __ldg(p + o10);
            float v11 = __ldg(p + o11);
            obase[(size_t)k * NIDX] = v00 * w00 + v01 * w01 + v10 * w10 + v11 * w11;
        }
    }
}

__global__ __launch_bounds__(TPB) void spatial_gather_kernel(
    const float* __restrict__ f0, const float* __restrict__ f1,
    const float* __restrict__ f2, const float* __restrict__ f3,
    const int*  __restrict__ indices, float* __restrict__ out)
{
    const int i = blockIdx.x * TPB + threadIdx.x;   // index position 0..4095
    const int g = blockIdx.y;                        // channel group (of CPT)
    const int b = blockIdx.z;                        // batch

    // Channel-group -> level map (uniform per block, no divergence):
    //   L0: 64ch  -> groups [0,8)    L1: 128ch -> groups [8,24)
    //   L2: 256ch -> groups [24,56)  L3: 512ch -> groups [56,120)
    if (g < 8) {
        sample_level<256, 64>(f0, indices, out, i, g * CPT, g * CPT, b);
    } else if (g < 24) {
        const int cl = (g - 8) * CPT;
        sample_level<128, 128>(f1, indices, out, i, cl, 64 + cl, b);
    } else if (g < 56) {
        const int cl = (g - 24) * CPT;
        sample_level<64, 256>(f2, indices, out, i, cl, 192 + cl, b);
    } else {
        const int cl = (g - 56) * CPT;
        sample_level<32, 512>(f3, indices, out, i, cl, 448 + cl, b);
    }
}

extern "C" void kernel_launch(void* const* d_in, const int* in_sizes, int n_in,
                              void* d_out, int out_size)
{
    const float* f0 = (const float*)d_in[0];
    const float* f1 = (const float*)d_in[1];
    const float* f2 = (const float*)d_in[2];
    const float* f3 = (const float*)d_in[3];
    const int* indices = (const int*)d_in[4];
    float* out = (float*)d_out;

    dim3 grid(NIDX / TPB, 960 / CPT, 4);   // 16 x 120 x 4
    dim3 block(TPB);
    spatial_gather_kernel<<<grid, block>>>(f0, f1, f2, f3, indices, out);
}

// round 11
// speedup vs baseline: 1.2740x; 1.2740x over previous
#include <cuda_runtime.h>

// 4 pyramids -> bilinear-resize to 256x256 (half-pixel, clamp-to-edge) ->
// gather 4096 flat indices -> concat channels. out [4, 960, 4096] fp32.
//
// R7 ncu: L1tex-bound (L1=63.6%, DRAM=22.8%) from address-divergent tap LDGs.
// Fix: stage f1/f2/f3 planes in padded shared memory (coalesced fills),
// do the scattered 4-tap sampling via LDS (cost = bank conflict degree ~3,
// vs ~25-32 L1tex wavefronts per divergent gmem load). f0 remains a direct
// identity gather (compulsory traffic).

#define NIDX 4096
#define TPB  256

// Bilinear geometry on source grid S, smem row pitch P (P % 32 == 4 ->
// bank = (x + 4y) % 32, randomized; P*4 % 16 == 0 -> float4-aligned fills).
template <int S, int P>
__device__ __forceinline__ void geom(int idx, int& o00, int& o01, int& o10, int& o11,
                                     float& w00, float& w01, float& w10, float& w11)
{
    const int y = idx >> 8;
    const int x = idx & 255;
    constexpr float scale = (float)S * (1.0f / 256.0f);
    const float fy = ((float)y + 0.5f) * scale - 0.5f;
    const float fx = ((float)x + 0.5f) * scale - 0.5f;
    const float fy0 = floorf(fy);
    const float fx0 = floorf(fx);
    const float wy = fy - fy0;
    const float wx = fx - fx0;
    const int iy0 = (int)fy0, ix0 = (int)fx0;
    const int y0 = min(max(iy0, 0), S - 1);
    const int y1 = min(max(iy0 + 1, 0), S - 1);
    const int x0 = min(max(ix0, 0), S - 1);
    const int x1 = min(max(ix0 + 1, 0), S - 1);
    o00 = y0 * P + x0;  o01 = y0 * P + x1;
    o10 = y1 * P + x0;  o11 = y1 * P + x1;
    w00 = (1.0f - wy) * (1.0f - wx);
    w01 = (1.0f - wy) * wx;
    w10 = wy * (1.0f - wx);
    w11 = wy * wx;
}

// ---------------- f0: identity gather (scale 1) ----------------
#define CPT0 8
__global__ __launch_bounds__(TPB) void k_f0(
    const float* __restrict__ f0, const int* __restrict__ indices,
    float* __restrict__ out)
{
    const int i = blockIdx.x * TPB + threadIdx.x;
    const int g = blockIdx.y;            // 8 groups of 8 channels
    const int b = blockIdx.z;
    const int idx = __ldg(indices + i);
    const float* base = f0 + ((size_t)(b * 64 + g * CPT0) << 16);
    float* ob = out + ((size_t)b * 960 + g * CPT0) * NIDX + i;
    #pragma unroll
    for (int k = 0; k < CPT0; k++)
        ob[(size_t)k * NIDX] = __ldg(base + ((size_t)k << 16) + idx);
}

// ---------------- f1: S=128, 1 channel per block, smem 128x132 ----------------
#define P1 132
__global__ __launch_bounds__(TPB) void k_f1(
    const float* __restrict__ f1, const int* __restrict__ indices,
    float* __restrict__ out)
{
    extern __shared__ float sm[];                 // 128 * 132 floats
    const int c = blockIdx.x;                     // 0..127
    const int b = blockIdx.y;
    const int t = threadIdx.x;

    const float4* p4 = (const float4*)(f1 + ((size_t)(b * 128 + c) << 14));
    #pragma unroll
    for (int k = 0; k < 16; k++) {                // 4096 float4 / 256 thr
        const int j4 = t + k * TPB;
        float4 v = __ldg(p4 + j4);
        const int y = j4 >> 5;                    // 32 float4 per row
        const int xq = j4 & 31;
        *(float4*)&sm[y * P1 + xq * 4] = v;
    }
    __syncthreads();

    float* ob = out + ((size_t)b * 960 + 64 + c) * NIDX;
    #pragma unroll 4
    for (int k = 0; k < 16; k++) {
        const int i = t + k * TPB;
        const int idx = __ldg(indices + i);
        int o00, o01, o10, o11; float w00, w01, w10, w11;
        geom<128, P1>(idx, o00, o01, o10, o11, w00, w01, w10, w11);
        ob[i] = sm[o00] * w00 + sm[o01] * w01 + sm[o10] * w10 + sm[o11] * w11;
    }
}

// ---------------- f2: S=64, 2 channels per block, smem 2 x 64x68 ----------------
#define P2 68
#define PL2 (64 * P2)                              // 4352 floats (mult of 32)
__global__ __launch_bounds__(TPB) void k_f2(
    const float* __restrict__ f2, const int* __restrict__ indices,
    float* __restrict__ out)
{
    extern __shared__ float sm[];                  // 2 * 4352 floats
    const int g = blockIdx.x;                      // 0..127 channel pairs
    const int b = blockIdx.y;
    const int t = threadIdx.x;

    const float* base = f2 + ((size_t)(b * 256 + g * 2) << 12);
    #pragma unroll
    for (int cc = 0; cc < 2; cc++) {
        const float4* p4 = (const float4*)(base + ((size_t)cc << 12));
        #pragma unroll
        for (int k = 0; k < 4; k++) {              // 1024 float4 / 256 thr
            const int j4 = t + k * TPB;
            float4 v = __ldg(p4 + j4);
            const int y = j4 >> 4;                 // 16 float4 per row
            const int xq = j4 & 15;
            *(float4*)&sm[cc * PL2 + y * P2 + xq * 4] = v;
        }
    }
    __syncthreads();

    float* ob = out + ((size_t)b * 960 + 192 + g * 2) * NIDX;
    #pragma unroll 2
    for (int k = 0; k < 16; k++) {
        const int i = t + k * TPB;
        const int idx = __ldg(indices + i);
        int o00, o01, o10, o11; float w00, w01, w10, w11;
        geom<64, P2>(idx, o00, o01, o10, o11, w00, w01, w10, w11);
        #pragma unroll
        for (int cc = 0; cc < 2; cc++) {
            const float* s = sm + cc * PL2;
            ob[(size_t)cc * NIDX + i] =
                s[o00] * w00 + s[o01] * w01 + s[o10] * w10 + s[o11] * w11;
        }
    }
}

// ---------------- f3: S=32, 4 channels per block, smem 4 x 32x36 ----------------
#define P3 36
#define PL3 (32 * P3)                              // 1152 floats (mult of 32)
__global__ __launch_bounds__(TPB) void k_f3(
    const float* __restrict__ f3, const int* __restrict__ indices,
    float* __restrict__ out)
{
    extern __shared__ float sm[];                  // 4 * 1152 floats
    const int g = blockIdx.x;                      // 0..127 channel quads
    const int b = blockIdx.y;
    const int t = threadIdx.x;

    const float* base = f3 + ((size_t)(b * 512 + g * 4) << 10);
    #pragma unroll
    for (int cc = 0; cc < 4; cc++) {
        const float4* p4 = (const float4*)(base + ((size_t)cc << 10));
        const int j4 = t;                          // 256 float4 per plane
        float4 v = __ldg(p4 + j4);
        const int y = j4 >> 3;                     // 8 float4 per row
        const int xq = j4 & 7;
        *(float4*)&sm[cc * PL3 + y * P3 + xq * 4] = v;
    }
    __syncthreads();

    float* ob = out + ((size_t)b * 960 + 448 + g * 4) * NIDX;
    #pragma unroll 2
    for (int k = 0; k < 16; k++) {
        const int i = t + k * TPB;
        const int idx = __ldg(indices + i);
        int o00, o01, o10, o11; float w00, w01, w10, w11;
        geom<32, P3>(idx, o00, o01, o10, o11, w00, w01, w10, w11);
        #pragma unroll
        for (int cc = 0; cc < 4; cc++) {
            const float* s = sm + cc * PL3;
            ob[(size_t)cc * NIDX + i] =
                s[o00] * w00 + s[o01] * w01 + s[o10] * w10 + s[o11] * w11;
        }
    }
}

extern "C" void kernel_launch(void* const* d_in, const int* in_sizes, int n_in,
                              void* d_out, int out_size)
{
    const float* f0 = (const float*)d_in[0];
    const float* f1 = (const float*)d_in[1];
    const float* f2 = (const float*)d_in[2];
    const float* f3 = (const float*)d_in[3];
    const int* indices = (const int*)d_in[4];
    float* out = (float*)d_out;

    const int smem1 = 128 * P1 * (int)sizeof(float);   // 67584 B > 48KB opt-in
    cudaFuncSetAttribute(k_f1, cudaFuncAttributeMaxDynamicSharedMemorySize, smem1);

    k_f0<<<dim3(NIDX / TPB, 8, 4), TPB>>>(f0, indices, out);
    k_f1<<<dim3(128, 4), TPB, smem1>>>(f1, indices, out);
    k_f2<<<dim3(128, 4), TPB, 2 * PL2 * (int)sizeof(float)>>>(f2, indices, out);
    k_f3<<<dim3(128, 4), TPB, 4 * PL3 * (int)sizeof(float)>>>(f3, indices, out);
}